// round 1
// baseline (speedup 1.0000x reference)
#include <cuda_runtime.h>
#include <cuda_bf16.h>
#include <math.h>

#define S_LEN   4096
#define DMODEL  1024
#define HD      128
#define NH      8

// Scratch (static __device__ globals; allocation-free as required).
// All stored pre-rounded to tf32 so attention mainloop does no cvt.
__device__ float g_q[S_LEN * DMODEL];  // [s][h*128+d], scaled by (1/sqrt(128))*log2(e)
__device__ float g_k[S_LEN * HD];      // [s][d]
__device__ float g_vt[HD * S_LEN];     // [d][s]  (transposed for PV B-fragments)

__device__ __forceinline__ unsigned f2tf(float f) {
    unsigned u;
    asm("cvt.rna.tf32.f32 %0, %1;" : "=r"(u) : "f"(f));
    return u;
}

__device__ __forceinline__ void mma_tf32(float* c, const unsigned* a, const unsigned* b) {
    asm volatile(
        "mma.sync.aligned.m16n8k8.row.col.f32.tf32.tf32.f32 "
        "{%0,%1,%2,%3}, {%4,%5,%6,%7}, {%8,%9}, {%0,%1,%2,%3};\n"
        : "+f"(c[0]), "+f"(c[1]), "+f"(c[2]), "+f"(c[3])
        : "r"(a[0]), "r"(a[1]), "r"(a[2]), "r"(a[3]),
          "r"(b[0]), "r"(b[1]));
}

// ---------------------------------------------------------------------------
// tf32 GEMM: C[M,N] = A[M,K] @ W[K,N] + bias, optional transposed store.
// Output values are tf32-rounded. outMul applied to (acc + bias).
// BM=128, BN=64, BK=32, 256 threads (8 warps, 4x2), warp tile 32x32.
// ---------------------------------------------------------------------------
#define GBM 128
#define GBN 64
#define GBK 32
#define GAP 36   // A smem row stride (32+4): a-frag LDS banks (4g+t) distinct
#define GWP 72   // W smem row stride (64+8): b-frag LDS banks (8t+g) distinct

__global__ __launch_bounds__(256)
void mqa_gemm_tf32(const float* __restrict__ A, const float* __restrict__ W,
                   const float* __restrict__ bias, float* __restrict__ C,
                   int M, int N, int K, int transC, float outMul)
{
    __shared__ float As[GBM * GAP];
    __shared__ float Ws[GBK * GWP];

    const int tid = threadIdx.x;
    const int m0 = blockIdx.y * GBM;
    const int n0 = blockIdx.x * GBN;
    const int w = tid >> 5, lane = tid & 31;
    const int wr = w >> 1, wc = w & 1;
    const int g = lane >> 2, t = lane & 3;
    const int mrow = wr * 32, ncol = wc * 32;

    float acc[2][4][4];
#pragma unroll
    for (int mi = 0; mi < 2; mi++)
#pragma unroll
        for (int ni = 0; ni < 4; ni++)
#pragma unroll
            for (int j = 0; j < 4; j++) acc[mi][ni][j] = 0.f;

    for (int k0 = 0; k0 < K; k0 += GBK) {
        // Load A tile 128x32 (tf32-round at store)
#pragma unroll
        for (int i = 0; i < 4; i++) {
            int idx = tid + 256 * i;
            int r = idx >> 3, c4 = (idx & 7) * 4;
            float4 v = *reinterpret_cast<const float4*>(&A[(size_t)(m0 + r) * K + k0 + c4]);
            float* d = &As[r * GAP + c4];
            d[0] = __uint_as_float(f2tf(v.x));
            d[1] = __uint_as_float(f2tf(v.y));
            d[2] = __uint_as_float(f2tf(v.z));
            d[3] = __uint_as_float(f2tf(v.w));
        }
        // Load W tile 32x64 (as-is layout [k][n], tf32-round)
#pragma unroll
        for (int i = 0; i < 2; i++) {
            int idx = tid + 256 * i;
            int r = idx >> 4, c4 = (idx & 15) * 4;
            float4 v = *reinterpret_cast<const float4*>(&W[(size_t)(k0 + r) * N + n0 + c4]);
            float* d = &Ws[r * GWP + c4];
            d[0] = __uint_as_float(f2tf(v.x));
            d[1] = __uint_as_float(f2tf(v.y));
            d[2] = __uint_as_float(f2tf(v.z));
            d[3] = __uint_as_float(f2tf(v.w));
        }
        __syncthreads();

#pragma unroll
        for (int ks = 0; ks < 4; ks++) {
            const int kk = ks * 8;
            unsigned ar[2][4];
#pragma unroll
            for (int mi = 0; mi < 2; mi++) {
                const float* base = &As[(mrow + mi * 16) * GAP + kk];
                ar[mi][0] = __float_as_uint(base[g * GAP + t]);
                ar[mi][1] = __float_as_uint(base[(g + 8) * GAP + t]);
                ar[mi][2] = __float_as_uint(base[g * GAP + t + 4]);
                ar[mi][3] = __float_as_uint(base[(g + 8) * GAP + t + 4]);
            }
            unsigned br[4][2];
#pragma unroll
            for (int ni = 0; ni < 4; ni++) {
                const float* base = &Ws[kk * GWP + ncol + ni * 8 + g];
                br[ni][0] = __float_as_uint(base[t * GWP]);
                br[ni][1] = __float_as_uint(base[(t + 4) * GWP]);
            }
#pragma unroll
            for (int mi = 0; mi < 2; mi++)
#pragma unroll
                for (int ni = 0; ni < 4; ni++)
                    mma_tf32(acc[mi][ni], ar[mi], br[ni]);
        }
        __syncthreads();
    }

    // Epilogue
#pragma unroll
    for (int mi = 0; mi < 2; mi++) {
#pragma unroll
        for (int ni = 0; ni < 4; ni++) {
            int row = m0 + mrow + mi * 16 + g;
            int col = n0 + ncol + ni * 8 + 2 * t;
            float b0 = bias[col], b1 = bias[col + 1];
            float v00 = (acc[mi][ni][0] + b0) * outMul;
            float v01 = (acc[mi][ni][1] + b1) * outMul;
            float v10 = (acc[mi][ni][2] + b0) * outMul;
            float v11 = (acc[mi][ni][3] + b1) * outMul;
            v00 = __uint_as_float(f2tf(v00));
            v01 = __uint_as_float(f2tf(v01));
            v10 = __uint_as_float(f2tf(v10));
            v11 = __uint_as_float(f2tf(v11));
            if (!transC) {
                *reinterpret_cast<float2*>(&C[(size_t)row * N + col]) = make_float2(v00, v01);
                *reinterpret_cast<float2*>(&C[(size_t)(row + 8) * N + col]) = make_float2(v10, v11);
            } else {
                C[(size_t)col * M + row] = v00;
                C[(size_t)(col + 1) * M + row] = v01;
                C[(size_t)col * M + row + 8] = v10;
                C[(size_t)(col + 1) * M + row + 8] = v11;
            }
        }
    }
}

// ---------------------------------------------------------------------------
// Flash attention (MQA): grid (S/64, NH), 128 threads (4 warps x 16 rows).
// BM=64 q rows, BN=32 kv tokens per iteration, d=128.
// Scores already in log2-domain (scale*log2e folded into q) -> exp2f.
// ---------------------------------------------------------------------------
#define FBM 64
#define FBN 32
#define QSTR 132  // 128+4: frag LDS banks (4x+y) distinct
#define VSTR 36   // 32+4

__global__ __launch_bounds__(128)
void mqa_flash(float* __restrict__ out)
{
    extern __shared__ float sm[];
    float* Qs = sm;                       // [64][132]
    float* Ks = Qs + FBM * QSTR;          // [32][132]
    float* Vt = Ks + FBN * QSTR;          // [128][36]
    float* Ps = Vt + HD * VSTR;           // [64][36]

    const int tid = threadIdx.x;
    const int w = tid >> 5, lane = tid & 31;
    const int g = lane >> 2, t = lane & 3;
    const int q0 = blockIdx.x * FBM;
    const int h = blockIdx.y;

    // Load Q tile (already tf32-rounded & scaled)
#pragma unroll
    for (int i = 0; i < 16; i++) {
        int idx = tid + 128 * i;
        int r = idx >> 5, c4 = (idx & 31) * 4;
        *reinterpret_cast<float4*>(&Qs[r * QSTR + c4]) =
            *reinterpret_cast<const float4*>(&g_q[(size_t)(q0 + r) * DMODEL + h * HD + c4]);
    }

    float oacc[16][4];
#pragma unroll
    for (int d = 0; d < 16; d++)
#pragma unroll
        for (int j = 0; j < 4; j++) oacc[d][j] = 0.f;
    float m0 = -1e30f, m1 = -1e30f, l0 = 0.f, l1 = 0.f;

    for (int kb = 0; kb < S_LEN; kb += FBN) {
        __syncthreads();  // prev-iter tile reads done; also orders Q load (iter 0)
        // K tile: 32 tokens x 128 dims
#pragma unroll
        for (int i = 0; i < 8; i++) {
            int idx = tid + 128 * i;
            int r = idx >> 5, c4 = (idx & 31) * 4;
            *reinterpret_cast<float4*>(&Ks[r * QSTR + c4]) =
                *reinterpret_cast<const float4*>(&g_k[(size_t)(kb + r) * HD + c4]);
        }
        // Vt tile: 128 dims x 32 tokens
#pragma unroll
        for (int i = 0; i < 8; i++) {
            int idx = tid + 128 * i;
            int r = idx >> 3, c4 = (idx & 7) * 4;
            *reinterpret_cast<float4*>(&Vt[r * VSTR + c4]) =
                *reinterpret_cast<const float4*>(&g_vt[(size_t)r * S_LEN + kb + c4]);
        }
        __syncthreads();

        // S = Q K^T  (warp rows: 16w .. 16w+15, all 32 cols)
        float sacc[4][4];
#pragma unroll
        for (int ni = 0; ni < 4; ni++)
#pragma unroll
            for (int j = 0; j < 4; j++) sacc[ni][j] = 0.f;

#pragma unroll
        for (int ks = 0; ks < 16; ks++) {
            const int kk = ks * 8;
            unsigned a[4];
            const float* qb = &Qs[(w * 16) * QSTR + kk];
            a[0] = __float_as_uint(qb[g * QSTR + t]);
            a[1] = __float_as_uint(qb[(g + 8) * QSTR + t]);
            a[2] = __float_as_uint(qb[g * QSTR + t + 4]);
            a[3] = __float_as_uint(qb[(g + 8) * QSTR + t + 4]);
#pragma unroll
            for (int ni = 0; ni < 4; ni++) {
                unsigned b[2];
                const float* kp = &Ks[(ni * 8 + g) * QSTR + kk];
                b[0] = __float_as_uint(kp[t]);
                b[1] = __float_as_uint(kp[t + 4]);
                mma_tf32(sacc[ni], a, b);
            }
        }

        // Online softmax (base-2). Thread owns rows g, g+8; cols 8ni+2t(+1).
        float tm0 = -1e30f, tm1 = -1e30f;
#pragma unroll
        for (int ni = 0; ni < 4; ni++) {
            tm0 = fmaxf(tm0, fmaxf(sacc[ni][0], sacc[ni][1]));
            tm1 = fmaxf(tm1, fmaxf(sacc[ni][2], sacc[ni][3]));
        }
        tm0 = fmaxf(tm0, __shfl_xor_sync(0xffffffffu, tm0, 1));
        tm0 = fmaxf(tm0, __shfl_xor_sync(0xffffffffu, tm0, 2));
        tm1 = fmaxf(tm1, __shfl_xor_sync(0xffffffffu, tm1, 1));
        tm1 = fmaxf(tm1, __shfl_xor_sync(0xffffffffu, tm1, 2));
        float mn0 = fmaxf(m0, tm0), mn1 = fmaxf(m1, tm1);
        float al0 = exp2f(m0 - mn0), al1 = exp2f(m1 - mn1);
        m0 = mn0; m1 = mn1;

        float p[4][4];
        float rs0 = 0.f, rs1 = 0.f;
#pragma unroll
        for (int ni = 0; ni < 4; ni++) {
            p[ni][0] = exp2f(sacc[ni][0] - mn0);
            p[ni][1] = exp2f(sacc[ni][1] - mn0);
            p[ni][2] = exp2f(sacc[ni][2] - mn1);
            p[ni][3] = exp2f(sacc[ni][3] - mn1);
            rs0 += p[ni][0] + p[ni][1];
            rs1 += p[ni][2] + p[ni][3];
        }
        rs0 += __shfl_xor_sync(0xffffffffu, rs0, 1);
        rs0 += __shfl_xor_sync(0xffffffffu, rs0, 2);
        rs1 += __shfl_xor_sync(0xffffffffu, rs1, 1);
        rs1 += __shfl_xor_sync(0xffffffffu, rs1, 2);
        l0 = l0 * al0 + rs0;
        l1 = l1 * al1 + rs1;
#pragma unroll
        for (int d = 0; d < 16; d++) {
            oacc[d][0] *= al0; oacc[d][1] *= al0;
            oacc[d][2] *= al1; oacc[d][3] *= al1;
        }
        // Store P (tf32-rounded) to warp-private smem rows
#pragma unroll
        for (int ni = 0; ni < 4; ni++) {
            *reinterpret_cast<float2*>(&Ps[(w * 16 + g) * VSTR + ni * 8 + 2 * t]) =
                make_float2(__uint_as_float(f2tf(p[ni][0])), __uint_as_float(f2tf(p[ni][1])));
            *reinterpret_cast<float2*>(&Ps[(w * 16 + g + 8) * VSTR + ni * 8 + 2 * t]) =
                make_float2(__uint_as_float(f2tf(p[ni][2])), __uint_as_float(f2tf(p[ni][3])));
        }
        __syncwarp();

        // O += P @ V   (B = Vt[d][token])
#pragma unroll
        for (int ks = 0; ks < 4; ks++) {
            const int kk = ks * 8;
            unsigned a[4];
            const float* pb = &Ps[(w * 16) * VSTR + kk];
            a[0] = __float_as_uint(pb[g * VSTR + t]);
            a[1] = __float_as_uint(pb[(g + 8) * VSTR + t]);
            a[2] = __float_as_uint(pb[g * VSTR + t + 4]);
            a[3] = __float_as_uint(pb[(g + 8) * VSTR + t + 4]);
#pragma unroll
            for (int ni = 0; ni < 16; ni++) {
                unsigned b[2];
                const float* vb = &Vt[(ni * 8 + g) * VSTR + kk];
                b[0] = __float_as_uint(vb[t]);
                b[1] = __float_as_uint(vb[t + 4]);
                mma_tf32(oacc[ni], a, b);
            }
        }
    }

    // Epilogue: normalize and store
    float inv0 = 1.f / l0, inv1 = 1.f / l1;
    const int row = q0 + w * 16 + g;
#pragma unroll
    for (int ni = 0; ni < 16; ni++) {
        int col = h * HD + ni * 8 + 2 * t;
        *reinterpret_cast<float2*>(&out[(size_t)row * DMODEL + col]) =
            make_float2(oacc[ni][0] * inv0, oacc[ni][1] * inv0);
        *reinterpret_cast<float2*>(&out[(size_t)(row + 8) * DMODEL + col]) =
            make_float2(oacc[ni][2] * inv1, oacc[ni][3] * inv1);
    }
}

// ---------------------------------------------------------------------------
extern "C" void kernel_launch(void* const* d_in, const int* in_sizes, int n_in,
                              void* d_out, int out_size)
{
    const float* x  = (const float*)d_in[0];
    const float* Wq = (const float*)d_in[1];
    const float* bq = (const float*)d_in[2];
    const float* Wk = (const float*)d_in[3];
    const float* bk = (const float*)d_in[4];
    const float* Wv = (const float*)d_in[5];
    const float* bv = (const float*)d_in[6];
    float* out = (float*)d_out;

    void *qp, *kp, *vp;
    cudaGetSymbolAddress(&qp, g_q);
    cudaGetSymbolAddress(&kp, g_k);
    cudaGetSymbolAddress(&vp, g_vt);

    // fold softmax scale and log2(e) into q so attention uses exp2
    const float qmul = 0.08838834764831845f * 1.4426950408889634f;

    mqa_gemm_tf32<<<dim3(DMODEL / GBN, S_LEN / GBM), 256>>>(
        x, Wq, bq, (float*)qp, S_LEN, DMODEL, DMODEL, 0, qmul);
    mqa_gemm_tf32<<<dim3(HD / GBN, S_LEN / GBM), 256>>>(
        x, Wk, bk, (float*)kp, S_LEN, HD, DMODEL, 0, 1.0f);
    mqa_gemm_tf32<<<dim3(HD / GBN, S_LEN / GBM), 256>>>(
        x, Wv, bv, (float*)vp, S_LEN, HD, DMODEL, 1, 1.0f);

    const int smem_bytes = (FBM * QSTR + FBN * QSTR + HD * VSTR + FBM * VSTR) * 4;
    cudaFuncSetAttribute(mqa_flash, cudaFuncAttributeMaxDynamicSharedMemorySize, smem_bytes);
    mqa_flash<<<dim3(S_LEN / FBM, NH), 128, smem_bytes>>>(out);
}

// round 4
// speedup vs baseline: 1.3974x; 1.3974x over previous
#include <cuda_runtime.h>
#include <cuda_bf16.h>
#include <math.h>
#include <cstdint>

#define S_LEN   4096
#define DMODEL  1024
#define HD      128
#define NH      8

// Scratch in fragment-packed layouts (built by GEMM epilogues):
// g_q: A-frags [qblk64][head][mtile4][ks16][lane32][4]   (scaled by scale*log2e, tf32-rounded)
// g_k: B-frags [tokblk8][ks16][lane32][2]                (tf32-rounded)
// g_v: B-frags [tile64][dblk16][ks8][lane32][2]          (tf32-rounded, token-interleaved
//       within each 8-chunk: token u -> k-slot 4*(u&1)+(u>>1), so P acc regs {c0,c2,c1,c3}
//       ARE the PV A-fragment with no shuffles)
__device__ float g_q[S_LEN * DMODEL];
__device__ float g_k[S_LEN * HD];
__device__ float g_v[S_LEN * HD];

__device__ __forceinline__ unsigned f2tf(float f) {
    unsigned u;
    asm("cvt.rna.tf32.f32 %0, %1;" : "=r"(u) : "f"(f));
    return u;
}

__device__ __forceinline__ void mma_tf32(float* c, const unsigned* a, const unsigned* b) {
    asm volatile(
        "mma.sync.aligned.m16n8k8.row.col.f32.tf32.tf32.f32 "
        "{%0,%1,%2,%3}, {%4,%5,%6,%7}, {%8,%9}, {%0,%1,%2,%3};\n"
        : "+f"(c[0]), "+f"(c[1]), "+f"(c[2]), "+f"(c[3])
        : "r"(a[0]), "r"(a[1]), "r"(a[2]), "r"(a[3]),
          "r"(b[0]), "r"(b[1]));
}

#define CP_ASYNC16(dst_u32, src_ptr) \
    asm volatile("cp.async.cg.shared.global [%0], [%1], 16;" \
                 :: "r"(dst_u32), "l"(src_ptr) : "memory")
#define CP_COMMIT() asm volatile("cp.async.commit_group;" ::: "memory")
#define CP_WAIT0()  asm volatile("cp.async.wait_group 0;" ::: "memory")

__device__ __forceinline__ uint32_t smem_u32(const void* p) {
    uint32_t a;
    asm("{ .reg .u64 t; cvta.to.shared.u64 t, %1; cvt.u32.u64 %0, t; }" : "=r"(a) : "l"(p));
    return a;
}

// Fragment-packed scatter addressing (mode 0=Q A-frag, 1=K B-frag, 2=V B-frag).
__device__ __forceinline__ int frag_addr(int mode, int row, int col) {
    if (mode == 0) {            // row = token, col = head*128 + d
        int head = col >> 7, d = col & 127;
        int qb = row >> 6, mt = (row >> 4) & 3, hi = (row >> 3) & 1, g = row & 7;
        int ks = d >> 3, thi = (d >> 2) & 1, t = d & 3;
        return ((((qb * 8 + head) * 4 + mt) * 16 + ks) * 32 + g * 4 + t) * 4 + hi + 2 * thi;
    } else if (mode == 1) {     // row = token, col = d
        int tb = row >> 3, g = row & 7;
        int ks = col >> 3, t = col & 3, jd = (col >> 2) & 1;
        return ((tb * 16 + ks) * 32 + g * 4 + t) * 2 + jd;
    } else {                    // row = token, col = d ; token-interleaved k-slots
        int tile = row >> 6, tl = row & 63;
        int ks = tl >> 3, u = tl & 7;
        int t = u >> 1, jt = u & 1;       // k-slot = 4*(u&1)+(u>>1): t_=u>>1, jt=u&1
        int nd = col >> 3, g = col & 7;
        return (((tile * 16 + nd) * 8 + ks) * 32 + g * 4 + t) * 2 + jt;
    }
}

// ===========================================================================
// Projection GEMMs: tf32 mma, BM=128 BN=64 BK=32; epilogue scatters into
// fragment-packed layouts.
// ===========================================================================
#define GBM 128
#define GBN 64
#define GBK 32
#define GAP 36
#define GWP 72

__global__ __launch_bounds__(256)
void mqa_gemm_tf32(const float* __restrict__ A, const float* __restrict__ W,
                   const float* __restrict__ bias, float* __restrict__ C,
                   int M, int N, int K, int mode, float outMul)
{
    __shared__ float As[GBM * GAP];
    __shared__ float Ws[GBK * GWP];

    const int tid = threadIdx.x;
    const int m0 = blockIdx.y * GBM;
    const int n0 = blockIdx.x * GBN;
    const int w = tid >> 5, lane = tid & 31;
    const int wr = w >> 1, wc = w & 1;
    const int g = lane >> 2, t = lane & 3;
    const int mrow = wr * 32, ncol = wc * 32;

    float acc[2][4][4];
#pragma unroll
    for (int mi = 0; mi < 2; mi++)
#pragma unroll
        for (int ni = 0; ni < 4; ni++)
#pragma unroll
            for (int j = 0; j < 4; j++) acc[mi][ni][j] = 0.f;

    for (int k0 = 0; k0 < K; k0 += GBK) {
#pragma unroll
        for (int i = 0; i < 4; i++) {
            int idx = tid + 256 * i;
            int r = idx >> 3, c4 = (idx & 7) * 4;
            float4 v = *reinterpret_cast<const float4*>(&A[(size_t)(m0 + r) * K + k0 + c4]);
            float* d = &As[r * GAP + c4];
            d[0] = __uint_as_float(f2tf(v.x));
            d[1] = __uint_as_float(f2tf(v.y));
            d[2] = __uint_as_float(f2tf(v.z));
            d[3] = __uint_as_float(f2tf(v.w));
        }
#pragma unroll
        for (int i = 0; i < 2; i++) {
            int idx = tid + 256 * i;
            int r = idx >> 4, c4 = (idx & 15) * 4;
            float4 v = *reinterpret_cast<const float4*>(&W[(size_t)(k0 + r) * N + n0 + c4]);
            float* d = &Ws[r * GWP + c4];
            d[0] = __uint_as_float(f2tf(v.x));
            d[1] = __uint_as_float(f2tf(v.y));
            d[2] = __uint_as_float(f2tf(v.z));
            d[3] = __uint_as_float(f2tf(v.w));
        }
        __syncthreads();

#pragma unroll
        for (int ks = 0; ks < 4; ks++) {
            const int kk = ks * 8;
            unsigned ar[2][4];
#pragma unroll
            for (int mi = 0; mi < 2; mi++) {
                const float* base = &As[(mrow + mi * 16) * GAP + kk];
                ar[mi][0] = __float_as_uint(base[g * GAP + t]);
                ar[mi][1] = __float_as_uint(base[(g + 8) * GAP + t]);
                ar[mi][2] = __float_as_uint(base[g * GAP + t + 4]);
                ar[mi][3] = __float_as_uint(base[(g + 8) * GAP + t + 4]);
            }
            unsigned br[4][2];
#pragma unroll
            for (int ni = 0; ni < 4; ni++) {
                const float* base = &Ws[kk * GWP + ncol + ni * 8 + g];
                br[ni][0] = __float_as_uint(base[t * GWP]);
                br[ni][1] = __float_as_uint(base[(t + 4) * GWP]);
            }
#pragma unroll
            for (int mi = 0; mi < 2; mi++)
#pragma unroll
                for (int ni = 0; ni < 4; ni++)
                    mma_tf32(acc[mi][ni], ar[mi], br[ni]);
        }
        __syncthreads();
    }

#pragma unroll
    for (int mi = 0; mi < 2; mi++) {
#pragma unroll
        for (int ni = 0; ni < 4; ni++) {
            int row = m0 + mrow + mi * 16 + g;
            int col = n0 + ncol + ni * 8 + 2 * t;
            float b0 = bias[col], b1 = bias[col + 1];
            float v00 = (acc[mi][ni][0] + b0) * outMul;
            float v01 = (acc[mi][ni][1] + b1) * outMul;
            float v10 = (acc[mi][ni][2] + b0) * outMul;
            float v11 = (acc[mi][ni][3] + b1) * outMul;
            C[frag_addr(mode, row,     col    )] = __uint_as_float(f2tf(v00));
            C[frag_addr(mode, row,     col + 1)] = __uint_as_float(f2tf(v01));
            C[frag_addr(mode, row + 8, col    )] = __uint_as_float(f2tf(v10));
            C[frag_addr(mode, row + 8, col + 1)] = __uint_as_float(f2tf(v11));
        }
    }
}

// ===========================================================================
// Flash attention: BM=64 q rows, BN=64 tokens, 4 warps (2x2 rows x tokens).
// Frag-packed operands, P reused in-register (no shuffles: V token-interleave
// makes the S accumulator layout == PV A-fragment layout), no-max softmax,
// cp.async double-buffered K/V.
// Smem (floats): Q[0..8192) K0[8192..) K1[16384..) V0[24576..) V1[32768..)
//                L[40960..41088);  Osm reuses K area at 8192 in epilogue.
// ===========================================================================
#define NITER (S_LEN / 64)
#define OFF_K0 8192
#define OFF_V0 24576
#define OFF_L  40960
#define SMEM_FLASH ((40960 + 128) * 4)

__global__ __launch_bounds__(128, 1)
void mqa_flash2(float* __restrict__ out)
{
    extern __shared__ float sm[];
    const uint32_t sbase = smem_u32(sm);
    const int tid = threadIdx.x;
    const int w = tid >> 5, lane = tid & 31;
    const int g = lane >> 2, t = lane & 3;
    const int wr = w >> 1, wc = w & 1;
    const int qb = blockIdx.x, head = blockIdx.y;

    // async tile copy: 32KB contiguous (8192 floats), 128 threads x 16 x 16B
    auto cpTile = [&](int dstOffFloats, const float* src) {
        uint32_t d0 = sbase + (uint32_t)dstOffFloats * 4 + (uint32_t)tid * 16;
        const float4* s = reinterpret_cast<const float4*>(src) + tid;
#pragma unroll
        for (int i = 0; i < 16; i++)
            CP_ASYNC16(d0 + (uint32_t)i * 2048, s + i * 128);
    };

    // prime: Q block + K/V tile 0
    cpTile(0, g_q + (size_t)(qb * 8 + head) * 8192);
    cpTile(OFF_K0, g_k);
    cpTile(OFF_V0, g_v);
    CP_COMMIT();
    CP_WAIT0();
    __syncthreads();

    float oacc[2][16][4];
#pragma unroll
    for (int mi = 0; mi < 2; mi++)
#pragma unroll
        for (int nd = 0; nd < 16; nd++)
#pragma unroll
            for (int j = 0; j < 4; j++) oacc[mi][nd][j] = 0.f;
    float ls[2][2] = {{0.f, 0.f}, {0.f, 0.f}};

#pragma unroll 1
    for (int it = 0; it < NITER; it++) {
        const int b = it & 1;
        const float* Kb = sm + OFF_K0 + b * 8192;
        const float* Vb = sm + OFF_V0 + b * 8192;

        // ---- S = Q K^T : warp tile 32 rows x 32 tokens ----
        float sacc[2][4][4];
#pragma unroll
        for (int mi = 0; mi < 2; mi++)
#pragma unroll
            for (int ni = 0; ni < 4; ni++)
#pragma unroll
                for (int j = 0; j < 4; j++) sacc[mi][ni][j] = 0.f;

#pragma unroll
        for (int ks = 0; ks < 16; ks++) {
            float4 af0 = *reinterpret_cast<const float4*>(
                &sm[(((2 * wr + 0) * 16 + ks) * 32 + lane) * 4]);
            float4 af1 = *reinterpret_cast<const float4*>(
                &sm[(((2 * wr + 1) * 16 + ks) * 32 + lane) * 4]);
#pragma unroll
            for (int ni = 0; ni < 4; ni++) {
                float2 bf = *reinterpret_cast<const float2*>(
                    &Kb[(((4 * wc + ni) * 16 + ks) * 32 + lane) * 2]);
                mma_tf32(sacc[0][ni], reinterpret_cast<const unsigned*>(&af0),
                         reinterpret_cast<const unsigned*>(&bf));
                mma_tf32(sacc[1][ni], reinterpret_cast<const unsigned*>(&af1),
                         reinterpret_cast<const unsigned*>(&bf));
            }
        }

        // prefetch next K into buffer 1-b (last read in iter it-1, done)
        if (it + 1 < NITER) {
            cpTile(OFF_K0 + (1 - b) * 8192, g_k + (size_t)(it + 1) * 8192);
            CP_COMMIT();
        }

        // ---- softmax (no max-sub; scores bounded): p=exp2(s), row sums ----
        {
            float lsa[2][2] = {{0.f, 0.f}, {0.f, 0.f}};
#pragma unroll
            for (int mi = 0; mi < 2; mi++)
#pragma unroll
                for (int ni = 0; ni < 4; ni++) {
                    float p0, p1, p2, p3;
                    asm("ex2.approx.ftz.f32 %0, %1;" : "=f"(p0) : "f"(sacc[mi][ni][0]));
                    asm("ex2.approx.ftz.f32 %0, %1;" : "=f"(p1) : "f"(sacc[mi][ni][1]));
                    asm("ex2.approx.ftz.f32 %0, %1;" : "=f"(p2) : "f"(sacc[mi][ni][2]));
                    asm("ex2.approx.ftz.f32 %0, %1;" : "=f"(p3) : "f"(sacc[mi][ni][3]));
                    lsa[mi][0] += p0 + p1;
                    lsa[mi][1] += p2 + p3;
                    sacc[mi][ni][0] = __uint_as_float(f2tf(p0));
                    sacc[mi][ni][1] = __uint_as_float(f2tf(p1));
                    sacc[mi][ni][2] = __uint_as_float(f2tf(p2));
                    sacc[mi][ni][3] = __uint_as_float(f2tf(p3));
                }
#pragma unroll
            for (int mi = 0; mi < 2; mi++)
#pragma unroll
                for (int hi = 0; hi < 2; hi++) {
                    float v = lsa[mi][hi];
                    v += __shfl_xor_sync(0xffffffffu, v, 1);
                    v += __shfl_xor_sync(0xffffffffu, v, 2);
                    ls[mi][hi] += v;
                }
        }

        // ---- O += P V : P acc regs {c0,c2,c1,c3} ARE the A fragment,
        //      because V's token order is interleaved to match (no shuffles) ----
#pragma unroll
        for (int ksp = 0; ksp < 4; ksp++) {
            unsigned a0[4], a1[4];
            a0[0] = __float_as_uint(sacc[0][ksp][0]);
            a0[1] = __float_as_uint(sacc[0][ksp][2]);
            a0[2] = __float_as_uint(sacc[0][ksp][1]);
            a0[3] = __float_as_uint(sacc[0][ksp][3]);
            a1[0] = __float_as_uint(sacc[1][ksp][0]);
            a1[1] = __float_as_uint(sacc[1][ksp][2]);
            a1[2] = __float_as_uint(sacc[1][ksp][1]);
            a1[3] = __float_as_uint(sacc[1][ksp][3]);
#pragma unroll
            for (int nd = 0; nd < 16; nd++) {
                float2 bf = *reinterpret_cast<const float2*>(
                    &Vb[((nd * 8 + 4 * wc + ksp) * 32 + lane) * 2]);
                mma_tf32(oacc[0][nd], a0, reinterpret_cast<const unsigned*>(&bf));
                mma_tf32(oacc[1][nd], a1, reinterpret_cast<const unsigned*>(&bf));
            }
        }

        // prefetch next V into buffer 1-b
        if (it + 1 < NITER) {
            cpTile(OFF_V0 + (1 - b) * 8192, g_v + (size_t)(it + 1) * 8192);
            CP_COMMIT();
        }
        CP_WAIT0();
        __syncthreads();
    }

    // ---- epilogue: combine wc halves via smem, divide by l, store ----
    if (t == 0) {
#pragma unroll
        for (int mi = 0; mi < 2; mi++)
#pragma unroll
            for (int hi = 0; hi < 2; hi++)
                sm[OFF_L + (32 * wr + mi * 16 + hi * 8 + g) * 2 + wc] = ls[mi][hi];
    }
    float* Osm = sm + OFF_K0;  // 64 x 132, reuses K buffers
    if (wc == 1) {
#pragma unroll
        for (int mi = 0; mi < 2; mi++)
#pragma unroll
            for (int nd = 0; nd < 16; nd++) {
                int r0 = 32 * wr + mi * 16 + g, col = nd * 8 + 2 * t;
                *reinterpret_cast<float2*>(&Osm[r0 * 132 + col]) =
                    make_float2(oacc[mi][nd][0], oacc[mi][nd][1]);
                *reinterpret_cast<float2*>(&Osm[(r0 + 8) * 132 + col]) =
                    make_float2(oacc[mi][nd][2], oacc[mi][nd][3]);
            }
    }
    __syncthreads();
    if (wc == 0) {
#pragma unroll
        for (int mi = 0; mi < 2; mi++) {
            int r0 = 32 * wr + mi * 16 + g;
            float inv0 = 1.f / (sm[OFF_L + r0 * 2] + sm[OFF_L + r0 * 2 + 1]);
            float inv1 = 1.f / (sm[OFF_L + (r0 + 8) * 2] + sm[OFF_L + (r0 + 8) * 2 + 1]);
#pragma unroll
            for (int nd = 0; nd < 16; nd++) {
                int col = nd * 8 + 2 * t;
                float2 q0 = *reinterpret_cast<float2*>(&Osm[r0 * 132 + col]);
                float2 q1 = *reinterpret_cast<float2*>(&Osm[(r0 + 8) * 132 + col]);
                float2 w0 = make_float2((q0.x + oacc[mi][nd][0]) * inv0,
                                        (q0.y + oacc[mi][nd][1]) * inv0);
                float2 w1 = make_float2((q1.x + oacc[mi][nd][2]) * inv1,
                                        (q1.y + oacc[mi][nd][3]) * inv1);
                *reinterpret_cast<float2*>(
                    &out[(size_t)(qb * 64 + r0) * DMODEL + head * HD + col]) = w0;
                *reinterpret_cast<float2*>(
                    &out[(size_t)(qb * 64 + r0 + 8) * DMODEL + head * HD + col]) = w1;
            }
        }
    }
}

// ===========================================================================
extern "C" void kernel_launch(void* const* d_in, const int* in_sizes, int n_in,
                              void* d_out, int out_size)
{
    const float* x  = (const float*)d_in[0];
    const float* Wq = (const float*)d_in[1];
    const float* bq = (const float*)d_in[2];
    const float* Wk = (const float*)d_in[3];
    const float* bk = (const float*)d_in[4];
    const float* Wv = (const float*)d_in[5];
    const float* bv = (const float*)d_in[6];
    float* out = (float*)d_out;

    void *qp, *kp, *vp;
    cudaGetSymbolAddress(&qp, g_q);
    cudaGetSymbolAddress(&kp, g_k);
    cudaGetSymbolAddress(&vp, g_v);

    // fold softmax scale and log2(e) into q so attention uses exp2
    const float qmul = 0.08838834764831845f * 1.4426950408889634f;

    mqa_gemm_tf32<<<dim3(DMODEL / GBN, S_LEN / GBM), 256>>>(
        x, Wq, bq, (float*)qp, S_LEN, DMODEL, DMODEL, 0, qmul);
    mqa_gemm_tf32<<<dim3(HD / GBN, S_LEN / GBM), 256>>>(
        x, Wk, bk, (float*)kp, S_LEN, HD, DMODEL, 1, 1.0f);
    mqa_gemm_tf32<<<dim3(HD / GBN, S_LEN / GBM), 256>>>(
        x, Wv, bv, (float*)vp, S_LEN, HD, DMODEL, 2, 1.0f);

    cudaFuncSetAttribute(mqa_flash2, cudaFuncAttributeMaxDynamicSharedMemorySize, SMEM_FLASH);
    mqa_flash2<<<dim3(S_LEN / 64, NH), 128, SMEM_FLASH>>>(out);
}

// round 5
// speedup vs baseline: 1.5949x; 1.1413x over previous
#include <cuda_runtime.h>
#include <cuda_bf16.h>
#include <math.h>
#include <cstdint>

#define S_LEN   4096
#define DMODEL  1024
#define HD      128
#define NH      8

// Scratch in fragment-packed layouts (built by GEMM epilogues):
// g_q: A-frags [qblk64][head][mtile4][ks16][lane32][4]   (scaled by scale*log2e, tf32-rounded)
// g_k: B-frags [tokblk8][ks16][lane32][2]                (tf32-rounded)
// g_v: B-frags [tile32][dblk16][ks4][lane32][2]          (tf32-rounded, token-interleaved
//       within each 8-chunk: token u -> k-slot 4*(u&1)+(u>>1), so P acc regs {c0,c2,c1,c3}
//       ARE the PV A-fragment with no shuffles)
__device__ float g_q[S_LEN * DMODEL];
__device__ float g_k[S_LEN * HD];
__device__ float g_v[S_LEN * HD];

__device__ __forceinline__ unsigned f2tf(float f) {
    unsigned u;
    asm("cvt.rna.tf32.f32 %0, %1;" : "=r"(u) : "f"(f));
    return u;
}

__device__ __forceinline__ void mma_tf32(float* c, const unsigned* a, const unsigned* b) {
    asm volatile(
        "mma.sync.aligned.m16n8k8.row.col.f32.tf32.tf32.f32 "
        "{%0,%1,%2,%3}, {%4,%5,%6,%7}, {%8,%9}, {%0,%1,%2,%3};\n"
        : "+f"(c[0]), "+f"(c[1]), "+f"(c[2]), "+f"(c[3])
        : "r"(a[0]), "r"(a[1]), "r"(a[2]), "r"(a[3]),
          "r"(b[0]), "r"(b[1]));
}

#define CP_ASYNC16(dst_u32, src_ptr) \
    asm volatile("cp.async.cg.shared.global [%0], [%1], 16;" \
                 :: "r"(dst_u32), "l"(src_ptr) : "memory")
#define CP_COMMIT() asm volatile("cp.async.commit_group;" ::: "memory")
#define CP_WAIT0()  asm volatile("cp.async.wait_group 0;" ::: "memory")

__device__ __forceinline__ uint32_t smem_u32(const void* p) {
    uint32_t a;
    asm("{ .reg .u64 t; cvta.to.shared.u64 t, %1; cvt.u32.u64 %0, t; }" : "=r"(a) : "l"(p));
    return a;
}

// Fragment-packed scatter addressing (mode 0=Q A-frag, 1=K B-frag, 2=V B-frag).
__device__ __forceinline__ int frag_addr(int mode, int row, int col) {
    if (mode == 0) {            // row = token, col = head*128 + d
        int head = col >> 7, d = col & 127;
        int qb = row >> 6, mt = (row >> 4) & 3, hi = (row >> 3) & 1, g = row & 7;
        int ks = d >> 3, thi = (d >> 2) & 1, t = d & 3;
        return ((((qb * 8 + head) * 4 + mt) * 16 + ks) * 32 + g * 4 + t) * 4 + hi + 2 * thi;
    } else if (mode == 1) {     // row = token, col = d
        int tb = row >> 3, g = row & 7;
        int ks = col >> 3, t = col & 3, jd = (col >> 2) & 1;
        return ((tb * 16 + ks) * 32 + g * 4 + t) * 2 + jd;
    } else {                    // row = token, col = d ; token-interleaved k-slots, 32-token tiles
        int tile = row >> 5, tl = row & 31;
        int ks = tl >> 3, u = tl & 7;
        int t = u >> 1, jt = u & 1;       // k-slot = 4*(u&1)+(u>>1)
        int nd = col >> 3, g = col & 7;
        return (((tile * 16 + nd) * 4 + ks) * 32 + g * 4 + t) * 2 + jt;
    }
}

// ===========================================================================
// Fused projection GEMM: one launch for Q, K, V.
// grid.x: [0,16) -> Q n-blocks, [16,18) -> K, [18,20) -> V.
// tf32 mma, BM=128 BN=64 BK=32, 256 threads; epilogue scatters frag-packed.
// ===========================================================================
#define GBM 128
#define GBN 64
#define GBK 32
#define GAP 36
#define GWP 72

__global__ __launch_bounds__(256)
void mqa_gemm_fused(const float* __restrict__ x,
                    const float* __restrict__ Wq, const float* __restrict__ bq,
                    const float* __restrict__ Wk, const float* __restrict__ bk,
                    const float* __restrict__ Wv, const float* __restrict__ bv,
                    float* __restrict__ Cq, float* __restrict__ Ck,
                    float* __restrict__ Cv, float qmul)
{
    __shared__ float As[GBM * GAP];
    __shared__ float Ws[GBK * GWP];

    const int bx = blockIdx.x;
    const float* W; const float* bias; float* C;
    int N, n0, mode; float outMul;
    if (bx < 16)      { W = Wq; bias = bq; C = Cq; N = DMODEL; n0 = bx * GBN;        mode = 0; outMul = qmul; }
    else if (bx < 18) { W = Wk; bias = bk; C = Ck; N = HD;     n0 = (bx - 16) * GBN; mode = 1; outMul = 1.f; }
    else              { W = Wv; bias = bv; C = Cv; N = HD;     n0 = (bx - 18) * GBN; mode = 2; outMul = 1.f; }

    const int K = DMODEL;
    const int tid = threadIdx.x;
    const int m0 = blockIdx.y * GBM;
    const int w = tid >> 5, lane = tid & 31;
    const int wr = w >> 1, wc = w & 1;
    const int g = lane >> 2, t = lane & 3;
    const int mrow = wr * 32, ncol = wc * 32;

    float acc[2][4][4];
#pragma unroll
    for (int mi = 0; mi < 2; mi++)
#pragma unroll
        for (int ni = 0; ni < 4; ni++)
#pragma unroll
            for (int j = 0; j < 4; j++) acc[mi][ni][j] = 0.f;

    for (int k0 = 0; k0 < K; k0 += GBK) {
#pragma unroll
        for (int i = 0; i < 4; i++) {
            int idx = tid + 256 * i;
            int r = idx >> 3, c4 = (idx & 7) * 4;
            float4 v = *reinterpret_cast<const float4*>(&x[(size_t)(m0 + r) * K + k0 + c4]);
            float* d = &As[r * GAP + c4];
            d[0] = __uint_as_float(f2tf(v.x));
            d[1] = __uint_as_float(f2tf(v.y));
            d[2] = __uint_as_float(f2tf(v.z));
            d[3] = __uint_as_float(f2tf(v.w));
        }
#pragma unroll
        for (int i = 0; i < 2; i++) {
            int idx = tid + 256 * i;
            int r = idx >> 4, c4 = (idx & 15) * 4;
            float4 v = *reinterpret_cast<const float4*>(&W[(size_t)(k0 + r) * N + n0 + c4]);
            float* d = &Ws[r * GWP + c4];
            d[0] = __uint_as_float(f2tf(v.x));
            d[1] = __uint_as_float(f2tf(v.y));
            d[2] = __uint_as_float(f2tf(v.z));
            d[3] = __uint_as_float(f2tf(v.w));
        }
        __syncthreads();

#pragma unroll
        for (int ks = 0; ks < 4; ks++) {
            const int kk = ks * 8;
            unsigned ar[2][4];
#pragma unroll
            for (int mi = 0; mi < 2; mi++) {
                const float* base = &As[(mrow + mi * 16) * GAP + kk];
                ar[mi][0] = __float_as_uint(base[g * GAP + t]);
                ar[mi][1] = __float_as_uint(base[(g + 8) * GAP + t]);
                ar[mi][2] = __float_as_uint(base[g * GAP + t + 4]);
                ar[mi][3] = __float_as_uint(base[(g + 8) * GAP + t + 4]);
            }
            unsigned br[4][2];
#pragma unroll
            for (int ni = 0; ni < 4; ni++) {
                const float* base = &Ws[kk * GWP + ncol + ni * 8 + g];
                br[ni][0] = __float_as_uint(base[t * GWP]);
                br[ni][1] = __float_as_uint(base[(t + 4) * GWP]);
            }
#pragma unroll
            for (int mi = 0; mi < 2; mi++)
#pragma unroll
                for (int ni = 0; ni < 4; ni++)
                    mma_tf32(acc[mi][ni], ar[mi], br[ni]);
        }
        __syncthreads();
    }

#pragma unroll
    for (int mi = 0; mi < 2; mi++) {
#pragma unroll
        for (int ni = 0; ni < 4; ni++) {
            int row = m0 + mrow + mi * 16 + g;
            int col = n0 + ncol + ni * 8 + 2 * t;
            float b0 = bias[col], b1 = bias[col + 1];
            float v00 = (acc[mi][ni][0] + b0) * outMul;
            float v01 = (acc[mi][ni][1] + b1) * outMul;
            float v10 = (acc[mi][ni][2] + b0) * outMul;
            float v11 = (acc[mi][ni][3] + b1) * outMul;
            C[frag_addr(mode, row,     col    )] = __uint_as_float(f2tf(v00));
            C[frag_addr(mode, row,     col + 1)] = __uint_as_float(f2tf(v01));
            C[frag_addr(mode, row + 8, col    )] = __uint_as_float(f2tf(v10));
            C[frag_addr(mode, row + 8, col + 1)] = __uint_as_float(f2tf(v11));
        }
    }
}

// ===========================================================================
// Flash attention: BM=64 q rows, BN=32 tokens/iter, 4 warps (2x2 rows x tokens),
// 2 CTAs/SM (96.5 KB smem). Frag-packed operands, P reused in-register
// (V token-interleave), no-max softmax, cp.async double-buffered K/V.
// Smem (floats): Q[0..8192) K0[8192..12288) K1[12288..16384)
//                V0[16384..20480) V1[20480..24576) L[24576..24704)
//                Osm (epilogue) reuses 8192.. (needs 8448 floats, fits)
// ===========================================================================
#define NITER (S_LEN / 32)
#define OFF_K0 8192
#define OFF_V0 16384
#define OFF_L  24576
#define SMEM_FLASH ((24576 + 128) * 4)

__global__ __launch_bounds__(128, 2)
void mqa_flash2(float* __restrict__ out)
{
    extern __shared__ float sm[];
    const uint32_t sbase = smem_u32(sm);
    const int tid = threadIdx.x;
    const int w = tid >> 5, lane = tid & 31;
    const int g = lane >> 2, t = lane & 3;
    const int wr = w >> 1, wc = w & 1;
    const int qb = blockIdx.x, head = blockIdx.y;

    // async 16KB tile copy (4096 floats): 128 threads x 8 x 16B
    auto cpTile = [&](int dstOffFloats, const float* src) {
        uint32_t d0 = sbase + (uint32_t)dstOffFloats * 4 + (uint32_t)tid * 16;
        const float4* s = reinterpret_cast<const float4*>(src) + tid;
#pragma unroll
        for (int i = 0; i < 8; i++)
            CP_ASYNC16(d0 + (uint32_t)i * 2048, s + i * 128);
    };
    // Q block: 32KB (8192 floats)
    {
        uint32_t d0 = sbase + (uint32_t)tid * 16;
        const float4* s = reinterpret_cast<const float4*>(g_q + (size_t)(qb * 8 + head) * 8192) + tid;
#pragma unroll
        for (int i = 0; i < 16; i++)
            CP_ASYNC16(d0 + (uint32_t)i * 2048, s + i * 128);
    }
    cpTile(OFF_K0, g_k);
    cpTile(OFF_V0, g_v);
    CP_COMMIT();
    CP_WAIT0();
    __syncthreads();

    float oacc[2][16][4];
#pragma unroll
    for (int mi = 0; mi < 2; mi++)
#pragma unroll
        for (int nd = 0; nd < 16; nd++)
#pragma unroll
            for (int j = 0; j < 4; j++) oacc[mi][nd][j] = 0.f;
    float ls[2][2] = {{0.f, 0.f}, {0.f, 0.f}};

#pragma unroll 1
    for (int it = 0; it < NITER; it++) {
        const int b = it & 1;
        const float* Kb = sm + OFF_K0 + b * 4096;
        const float* Vb = sm + OFF_V0 + b * 4096;

        // ---- S = Q K^T : warp tile 32 rows x 16 tokens ----
        float sacc[2][2][4];
#pragma unroll
        for (int mi = 0; mi < 2; mi++)
#pragma unroll
            for (int ni = 0; ni < 2; ni++)
#pragma unroll
                for (int j = 0; j < 4; j++) sacc[mi][ni][j] = 0.f;

#pragma unroll
        for (int ks = 0; ks < 16; ks++) {
            float4 af0 = *reinterpret_cast<const float4*>(
                &sm[(((2 * wr + 0) * 16 + ks) * 32 + lane) * 4]);
            float4 af1 = *reinterpret_cast<const float4*>(
                &sm[(((2 * wr + 1) * 16 + ks) * 32 + lane) * 4]);
#pragma unroll
            for (int ni = 0; ni < 2; ni++) {
                float2 bf = *reinterpret_cast<const float2*>(
                    &Kb[(((2 * wc + ni) * 16 + ks) * 32 + lane) * 2]);
                mma_tf32(sacc[0][ni], reinterpret_cast<const unsigned*>(&af0),
                         reinterpret_cast<const unsigned*>(&bf));
                mma_tf32(sacc[1][ni], reinterpret_cast<const unsigned*>(&af1),
                         reinterpret_cast<const unsigned*>(&bf));
            }
        }

        // prefetch next K into buffer 1-b (last read in iter it-1, done)
        if (it + 1 < NITER) {
            cpTile(OFF_K0 + (1 - b) * 4096, g_k + (size_t)(it + 1) * 4096);
            CP_COMMIT();
        }

        // ---- softmax (no max-sub; scores bounded): p=exp2(s), row sums ----
        {
            float lsa[2][2] = {{0.f, 0.f}, {0.f, 0.f}};
#pragma unroll
            for (int mi = 0; mi < 2; mi++)
#pragma unroll
                for (int ni = 0; ni < 2; ni++) {
                    float p0, p1, p2, p3;
                    asm("ex2.approx.ftz.f32 %0, %1;" : "=f"(p0) : "f"(sacc[mi][ni][0]));
                    asm("ex2.approx.ftz.f32 %0, %1;" : "=f"(p1) : "f"(sacc[mi][ni][1]));
                    asm("ex2.approx.ftz.f32 %0, %1;" : "=f"(p2) : "f"(sacc[mi][ni][2]));
                    asm("ex2.approx.ftz.f32 %0, %1;" : "=f"(p3) : "f"(sacc[mi][ni][3]));
                    lsa[mi][0] += p0 + p1;
                    lsa[mi][1] += p2 + p3;
                    sacc[mi][ni][0] = __uint_as_float(f2tf(p0));
                    sacc[mi][ni][1] = __uint_as_float(f2tf(p1));
                    sacc[mi][ni][2] = __uint_as_float(f2tf(p2));
                    sacc[mi][ni][3] = __uint_as_float(f2tf(p3));
                }
#pragma unroll
            for (int mi = 0; mi < 2; mi++)
#pragma unroll
                for (int hi = 0; hi < 2; hi++) {
                    float v = lsa[mi][hi];
                    v += __shfl_xor_sync(0xffffffffu, v, 1);
                    v += __shfl_xor_sync(0xffffffffu, v, 2);
                    ls[mi][hi] += v;
                }
        }

        // ---- O += P V : P acc regs {c0,c2,c1,c3} ARE the A fragment ----
#pragma unroll
        for (int ksp = 0; ksp < 2; ksp++) {
            unsigned a0[4], a1[4];
            a0[0] = __float_as_uint(sacc[0][ksp][0]);
            a0[1] = __float_as_uint(sacc[0][ksp][2]);
            a0[2] = __float_as_uint(sacc[0][ksp][1]);
            a0[3] = __float_as_uint(sacc[0][ksp][3]);
            a1[0] = __float_as_uint(sacc[1][ksp][0]);
            a1[1] = __float_as_uint(sacc[1][ksp][2]);
            a1[2] = __float_as_uint(sacc[1][ksp][1]);
            a1[3] = __float_as_uint(sacc[1][ksp][3]);
#pragma unroll
            for (int nd = 0; nd < 16; nd++) {
                float2 bf = *reinterpret_cast<const float2*>(
                    &Vb[((nd * 4 + 2 * wc + ksp) * 32 + lane) * 2]);
                mma_tf32(oacc[0][nd], a0, reinterpret_cast<const unsigned*>(&bf));
                mma_tf32(oacc[1][nd], a1, reinterpret_cast<const unsigned*>(&bf));
            }
        }

        // prefetch next V into buffer 1-b
        if (it + 1 < NITER) {
            cpTile(OFF_V0 + (1 - b) * 4096, g_v + (size_t)(it + 1) * 4096);
            CP_COMMIT();
        }
        CP_WAIT0();
        __syncthreads();
    }

    // ---- epilogue: combine wc halves via smem, divide by l, store ----
    if (t == 0) {
#pragma unroll
        for (int mi = 0; mi < 2; mi++)
#pragma unroll
            for (int hi = 0; hi < 2; hi++)
                sm[OFF_L + (32 * wr + mi * 16 + hi * 8 + g) * 2 + wc] = ls[mi][hi];
    }
    float* Osm = sm + OFF_K0;  // 64 x 132 floats, reuses K/V buffers
    if (wc == 1) {
#pragma unroll
        for (int mi = 0; mi < 2; mi++)
#pragma unroll
            for (int nd = 0; nd < 16; nd++) {
                int r0 = 32 * wr + mi * 16 + g, col = nd * 8 + 2 * t;
                *reinterpret_cast<float2*>(&Osm[r0 * 132 + col]) =
                    make_float2(oacc[mi][nd][0], oacc[mi][nd][1]);
                *reinterpret_cast<float2*>(&Osm[(r0 + 8) * 132 + col]) =
                    make_float2(oacc[mi][nd][2], oacc[mi][nd][3]);
            }
    }
    __syncthreads();
    if (wc == 0) {
#pragma unroll
        for (int mi = 0; mi < 2; mi++) {
            int r0 = 32 * wr + mi * 16 + g;
            float inv0 = 1.f / (sm[OFF_L + r0 * 2] + sm[OFF_L + r0 * 2 + 1]);
            float inv1 = 1.f / (sm[OFF_L + (r0 + 8) * 2] + sm[OFF_L + (r0 + 8) * 2 + 1]);
#pragma unroll
            for (int nd = 0; nd < 16; nd++) {
                int col = nd * 8 + 2 * t;
                float2 q0 = *reinterpret_cast<float2*>(&Osm[r0 * 132 + col]);
                float2 q1 = *reinterpret_cast<float2*>(&Osm[(r0 + 8) * 132 + col]);
                float2 w0 = make_float2((q0.x + oacc[mi][nd][0]) * inv0,
                                        (q0.y + oacc[mi][nd][1]) * inv0);
                float2 w1 = make_float2((q1.x + oacc[mi][nd][2]) * inv1,
                                        (q1.y + oacc[mi][nd][3]) * inv1);
                *reinterpret_cast<float2*>(
                    &out[(size_t)(qb * 64 + r0) * DMODEL + head * HD + col]) = w0;
                *reinterpret_cast<float2*>(
                    &out[(size_t)(qb * 64 + r0 + 8) * DMODEL + head * HD + col]) = w1;
            }
        }
    }
}

// ===========================================================================
extern "C" void kernel_launch(void* const* d_in, const int* in_sizes, int n_in,
                              void* d_out, int out_size)
{
    const float* x  = (const float*)d_in[0];
    const float* Wq = (const float*)d_in[1];
    const float* bq = (const float*)d_in[2];
    const float* Wk = (const float*)d_in[3];
    const float* bk = (const float*)d_in[4];
    const float* Wv = (const float*)d_in[5];
    const float* bv = (const float*)d_in[6];
    float* out = (float*)d_out;

    void *qp, *kp, *vp;
    cudaGetSymbolAddress(&qp, g_q);
    cudaGetSymbolAddress(&kp, g_k);
    cudaGetSymbolAddress(&vp, g_v);

    // fold softmax scale and log2(e) into q so attention uses exp2
    const float qmul = 0.08838834764831845f * 1.4426950408889634f;

    mqa_gemm_fused<<<dim3(20, S_LEN / GBM), 256>>>(
        x, Wq, bq, Wk, bk, Wv, bv, (float*)qp, (float*)kp, (float*)vp, qmul);

    cudaFuncSetAttribute(mqa_flash2, cudaFuncAttributeMaxDynamicSharedMemorySize, SMEM_FLASH);
    mqa_flash2<<<dim3(S_LEN / 64, NH), 128, SMEM_FLASH>>>(out);
}

// round 6
// speedup vs baseline: 2.6935x; 1.6889x over previous
#include <cuda_runtime.h>
#include <cuda_bf16.h>
#include <cuda_fp16.h>
#include <math.h>
#include <cstdint>

#define S_LEN   4096
#define DMODEL  1024
#define HD      128
#define NH      8

// Scratch: f16 fragment-packed layouts for m16n8k16 mma (built by GEMM epilogue).
// g_q: A-frags [qb64][head][warp4][ks8][lane32][reg4] (u32=f16x2), scaled by scale*log2e
// g_k: B-frags [tokblk8][ks8][lane32][reg2]
// g_v: B-frags [tile32][nd16][ksp2][lane32][reg2][e2] (half elements)
__device__ __align__(16) uint32_t g_q[S_LEN * DMODEL / 2];
__device__ __align__(16) uint32_t g_k[S_LEN * HD / 2];
__device__ __align__(16) __half   g_v[S_LEN * HD];

__device__ __forceinline__ unsigned f2tf(float f) {
    unsigned u;
    asm("cvt.rna.tf32.f32 %0, %1;" : "=r"(u) : "f"(f));
    return u;
}
__device__ __forceinline__ uint32_t packh2(float lo, float hi) {
    __half2 h = __floats2half2_rn(lo, hi);
    return *reinterpret_cast<uint32_t*>(&h);
}

__device__ __forceinline__ void mma_tf32(float* c, const unsigned* a, const unsigned* b) {
    asm volatile(
        "mma.sync.aligned.m16n8k8.row.col.f32.tf32.tf32.f32 "
        "{%0,%1,%2,%3}, {%4,%5,%6,%7}, {%8,%9}, {%0,%1,%2,%3};\n"
        : "+f"(c[0]), "+f"(c[1]), "+f"(c[2]), "+f"(c[3])
        : "r"(a[0]), "r"(a[1]), "r"(a[2]), "r"(a[3]),
          "r"(b[0]), "r"(b[1]));
}
__device__ __forceinline__ void mma_f16(float* c, const unsigned* a, const unsigned* b) {
    asm volatile(
        "mma.sync.aligned.m16n8k16.row.col.f32.f16.f16.f32 "
        "{%0,%1,%2,%3}, {%4,%5,%6,%7}, {%8,%9}, {%0,%1,%2,%3};\n"
        : "+f"(c[0]), "+f"(c[1]), "+f"(c[2]), "+f"(c[3])
        : "r"(a[0]), "r"(a[1]), "r"(a[2]), "r"(a[3]),
          "r"(b[0]), "r"(b[1]));
}

#define CP_ASYNC16(dst_u32, src_ptr) \
    asm volatile("cp.async.cg.shared.global [%0], [%1], 16;" \
                 :: "r"(dst_u32), "l"(src_ptr) : "memory")
#define CP_COMMIT() asm volatile("cp.async.commit_group;" ::: "memory")
#define CP_WAIT0()  asm volatile("cp.async.wait_group 0;" ::: "memory")

__device__ __forceinline__ uint32_t smem_u32(const void* p) {
    uint32_t a;
    asm("{ .reg .u64 t; cvta.to.shared.u64 t, %1; cvt.u32.u64 %0, t; }" : "=r"(a) : "l"(p));
    return a;
}

// ---- f16 fragment scatter indices (for GEMM epilogue) ----
// Q A-frag (m16n8k16): reg = kb*2 + hi ; value pair (col even, col+1) = one f16x2
__device__ __forceinline__ int qfrag_u32(int row, int col) {
    int head = col >> 7, d = col & 127;
    int qb = row >> 6, mt = (row >> 4) & 3, hi = (row >> 3) & 1, g = row & 7;
    int ks = d >> 4, kb = (d >> 3) & 1, t = (d >> 1) & 3;
    return ((((qb * 8 + head) * 4 + mt) * 8 + ks) * 32 + g * 4 + t) * 4 + kb * 2 + hi;
}
// K B-frag: n = token, k = dim
__device__ __forceinline__ int kfrag_u32(int row, int col) {
    int tb = row >> 3, g = row & 7;
    int ks = col >> 4, kb = (col >> 3) & 1, t = (col >> 1) & 3;
    return ((tb * 8 + ks) * 32 + g * 4 + t) * 2 + kb;
}
// V B-frag: n = dim, k = token (half-element index)
__device__ __forceinline__ int vfrag_half(int row, int col) {
    int tile = row >> 5, ksp = (row >> 4) & 1, slot = row & 15;
    int kb = slot >> 3, t = (slot >> 1) & 3, e = row & 1;
    int nd = col >> 3, g = col & 7;
    return ((((tile * 16 + nd) * 2 + ksp) * 32 + g * 4 + t) * 2 + kb) * 2 + e;
}

// ===========================================================================
// Fused projection GEMM (tf32 compute): grid.x [0,16)=Q, [16,18)=K, [18,20)=V.
// Epilogue converts to f16 and scatters fragment-packed.
// ===========================================================================
#define GBM 128
#define GBN 64
#define GBK 32
#define GAP 36
#define GWP 72

__global__ __launch_bounds__(256)
void mqa_gemm_fused(const float* __restrict__ x,
                    const float* __restrict__ Wq, const float* __restrict__ bq,
                    const float* __restrict__ Wk, const float* __restrict__ bk,
                    const float* __restrict__ Wv, const float* __restrict__ bv,
                    uint32_t* __restrict__ Cq, uint32_t* __restrict__ Ck,
                    __half* __restrict__ Cv, float qmul)
{
    __shared__ float As[GBM * GAP];
    __shared__ float Ws[GBK * GWP];

    const int bx = blockIdx.x;
    const float* W; const float* bias;
    int N, n0, mode; float outMul;
    if (bx < 16)      { W = Wq; bias = bq; N = DMODEL; n0 = bx * GBN;        mode = 0; outMul = qmul; }
    else if (bx < 18) { W = Wk; bias = bk; N = HD;     n0 = (bx - 16) * GBN; mode = 1; outMul = 1.f; }
    else              { W = Wv; bias = bv; N = HD;     n0 = (bx - 18) * GBN; mode = 2; outMul = 1.f; }

    const int K = DMODEL;
    const int tid = threadIdx.x;
    const int m0 = blockIdx.y * GBM;
    const int w = tid >> 5, lane = tid & 31;
    const int wr = w >> 1, wc = w & 1;
    const int g = lane >> 2, t = lane & 3;
    const int mrow = wr * 32, ncol = wc * 32;

    float acc[2][4][4];
#pragma unroll
    for (int mi = 0; mi < 2; mi++)
#pragma unroll
        for (int ni = 0; ni < 4; ni++)
#pragma unroll
            for (int j = 0; j < 4; j++) acc[mi][ni][j] = 0.f;

    for (int k0 = 0; k0 < K; k0 += GBK) {
#pragma unroll
        for (int i = 0; i < 4; i++) {
            int idx = tid + 256 * i;
            int r = idx >> 3, c4 = (idx & 7) * 4;
            float4 v = *reinterpret_cast<const float4*>(&x[(size_t)(m0 + r) * K + k0 + c4]);
            float* d = &As[r * GAP + c4];
            d[0] = __uint_as_float(f2tf(v.x));
            d[1] = __uint_as_float(f2tf(v.y));
            d[2] = __uint_as_float(f2tf(v.z));
            d[3] = __uint_as_float(f2tf(v.w));
        }
#pragma unroll
        for (int i = 0; i < 2; i++) {
            int idx = tid + 256 * i;
            int r = idx >> 4, c4 = (idx & 15) * 4;
            float4 v = *reinterpret_cast<const float4*>(&W[(size_t)(k0 + r) * N + n0 + c4]);
            float* d = &Ws[r * GWP + c4];
            d[0] = __uint_as_float(f2tf(v.x));
            d[1] = __uint_as_float(f2tf(v.y));
            d[2] = __uint_as_float(f2tf(v.z));
            d[3] = __uint_as_float(f2tf(v.w));
        }
        __syncthreads();

#pragma unroll
        for (int ks = 0; ks < 4; ks++) {
            const int kk = ks * 8;
            unsigned ar[2][4];
#pragma unroll
            for (int mi = 0; mi < 2; mi++) {
                const float* base = &As[(mrow + mi * 16) * GAP + kk];
                ar[mi][0] = __float_as_uint(base[g * GAP + t]);
                ar[mi][1] = __float_as_uint(base[(g + 8) * GAP + t]);
                ar[mi][2] = __float_as_uint(base[g * GAP + t + 4]);
                ar[mi][3] = __float_as_uint(base[(g + 8) * GAP + t + 4]);
            }
            unsigned br[4][2];
#pragma unroll
            for (int ni = 0; ni < 4; ni++) {
                const float* base = &Ws[kk * GWP + ncol + ni * 8 + g];
                br[ni][0] = __float_as_uint(base[t * GWP]);
                br[ni][1] = __float_as_uint(base[(t + 4) * GWP]);
            }
#pragma unroll
            for (int mi = 0; mi < 2; mi++)
#pragma unroll
                for (int ni = 0; ni < 4; ni++)
                    mma_tf32(acc[mi][ni], ar[mi], br[ni]);
        }
        __syncthreads();
    }

#pragma unroll
    for (int mi = 0; mi < 2; mi++) {
#pragma unroll
        for (int ni = 0; ni < 4; ni++) {
            int row = m0 + mrow + mi * 16 + g;
            int col = n0 + ncol + ni * 8 + 2 * t;
            float b0 = bias[col], b1 = bias[col + 1];
            float v00 = (acc[mi][ni][0] + b0) * outMul;
            float v01 = (acc[mi][ni][1] + b1) * outMul;
            float v10 = (acc[mi][ni][2] + b0) * outMul;
            float v11 = (acc[mi][ni][3] + b1) * outMul;
            if (mode == 0) {
                Cq[qfrag_u32(row,     col)] = packh2(v00, v01);
                Cq[qfrag_u32(row + 8, col)] = packh2(v10, v11);
            } else if (mode == 1) {
                Ck[kfrag_u32(row,     col)] = packh2(v00, v01);
                Ck[kfrag_u32(row + 8, col)] = packh2(v10, v11);
            } else {
                Cv[vfrag_half(row,     col    )] = __float2half_rn(v00);
                Cv[vfrag_half(row,     col + 1)] = __float2half_rn(v01);
                Cv[vfrag_half(row + 8, col    )] = __float2half_rn(v10);
                Cv[vfrag_half(row + 8, col + 1)] = __float2half_rn(v11);
            }
        }
    }
}

// ===========================================================================
// Flash attention (f16): BM=64, 4 warps row-split (16 rows each), BN=32
// tokens/iter. Q in registers (loaded once), K/V f16 double-buffered (8KB
// tiles, 32KB smem total), no-max softmax, deferred l-reduction, no O combine.
// ===========================================================================
#define FNITER (S_LEN / 32)

__global__ __launch_bounds__(128, 2)
void mqa_flash3(float* __restrict__ out)
{
    __shared__ __align__(16) uint32_t sm[8192];  // K0[0..2048) K1[2048..) V0[4096..) V1[6144..)
    const uint32_t sbase = smem_u32(sm);
    const int tid = threadIdx.x;
    const int w = tid >> 5, lane = tid & 31;
    const int qb = blockIdx.x, head = blockIdx.y;

    // ---- Q A-frags to registers (once) ----
    unsigned qa[8][4];
    {
        const uint4* qp = reinterpret_cast<const uint4*>(g_q)
                        + ((((size_t)(qb * 8 + head) * 4 + w) * 8) * 32 + lane);
#pragma unroll
        for (int ks = 0; ks < 8; ks++) {
            uint4 v = qp[ks * 32];
            qa[ks][0] = v.x; qa[ks][1] = v.y; qa[ks][2] = v.z; qa[ks][3] = v.w;
        }
    }

    // 8KB tile copy: 128 threads x 4 x 16B
    auto cpTile = [&](int dstU32, const uint32_t* src) {
        uint32_t d0 = sbase + (uint32_t)dstU32 * 4 + (uint32_t)tid * 16;
        const uint4* s = reinterpret_cast<const uint4*>(src) + tid;
#pragma unroll
        for (int i = 0; i < 4; i++)
            CP_ASYNC16(d0 + (uint32_t)i * 2048, s + i * 128);
    };

    cpTile(0, g_k);
    cpTile(4096, reinterpret_cast<const uint32_t*>(g_v));
    CP_COMMIT();
    CP_WAIT0();
    __syncthreads();

    float oacc[16][4];
#pragma unroll
    for (int nd = 0; nd < 16; nd++)
#pragma unroll
        for (int j = 0; j < 4; j++) oacc[nd][j] = 0.f;
    float l0 = 0.f, l1 = 0.f;

#pragma unroll 1
    for (int it = 0; it < FNITER; it++) {
        const int b = it & 1;
        const int Koff = b * 2048, Voff = 4096 + b * 2048;

        // ---- S = Q K^T : 16 rows x 32 tokens per warp ----
        float sacc[4][4];
#pragma unroll
        for (int ni = 0; ni < 4; ni++)
#pragma unroll
            for (int j = 0; j < 4; j++) sacc[ni][j] = 0.f;
#pragma unroll
        for (int ks = 0; ks < 8; ks++)
#pragma unroll
            for (int ni = 0; ni < 4; ni++) {
                uint2 kb = *reinterpret_cast<const uint2*>(
                    &sm[Koff + ((ni * 8 + ks) * 32 + lane) * 2]);
                mma_f16(sacc[ni], qa[ks], &kb.x);
            }

        // prefetch next K (buffer 1-b idle)
        if (it + 1 < FNITER) {
            cpTile((1 - b) * 2048, g_k + (size_t)(it + 1) * 2048);
            CP_COMMIT();
        }

        // ---- softmax (no max-sub): p = exp2(s); pack P as f16 A-frags ----
        unsigned pa[2][4];
#pragma unroll
        for (int ni = 0; ni < 4; ni++) {
            float p0, p1, p2, p3;
            asm("ex2.approx.ftz.f32 %0, %1;" : "=f"(p0) : "f"(sacc[ni][0]));
            asm("ex2.approx.ftz.f32 %0, %1;" : "=f"(p1) : "f"(sacc[ni][1]));
            asm("ex2.approx.ftz.f32 %0, %1;" : "=f"(p2) : "f"(sacc[ni][2]));
            asm("ex2.approx.ftz.f32 %0, %1;" : "=f"(p3) : "f"(sacc[ni][3]));
            l0 += p0 + p1;
            l1 += p2 + p3;
            pa[ni >> 1][(ni & 1) * 2 + 0] = packh2(p0, p1);
            pa[ni >> 1][(ni & 1) * 2 + 1] = packh2(p2, p3);
        }

        // ---- O += P V ----
#pragma unroll
        for (int ksp = 0; ksp < 2; ksp++)
#pragma unroll
            for (int nd = 0; nd < 16; nd++) {
                uint2 vb = *reinterpret_cast<const uint2*>(
                    &sm[Voff + ((nd * 2 + ksp) * 32 + lane) * 2]);
                mma_f16(oacc[nd], pa[ksp], &vb.x);
            }

        // prefetch next V
        if (it + 1 < FNITER) {
            cpTile(4096 + (1 - b) * 2048,
                   reinterpret_cast<const uint32_t*>(g_v) + (size_t)(it + 1) * 2048);
            CP_COMMIT();
        }
        CP_WAIT0();
        __syncthreads();
    }

    // ---- epilogue: reduce l across t-group, normalize, store ----
    l0 += __shfl_xor_sync(0xffffffffu, l0, 1);
    l0 += __shfl_xor_sync(0xffffffffu, l0, 2);
    l1 += __shfl_xor_sync(0xffffffffu, l1, 1);
    l1 += __shfl_xor_sync(0xffffffffu, l1, 2);
    const float inv0 = 1.f / l0, inv1 = 1.f / l1;
    const int g = lane >> 2, t = lane & 3;
    const int row0 = qb * 64 + w * 16 + g;
#pragma unroll
    for (int nd = 0; nd < 16; nd++) {
        int col = head * HD + nd * 8 + 2 * t;
        *reinterpret_cast<float2*>(&out[(size_t)row0 * DMODEL + col]) =
            make_float2(oacc[nd][0] * inv0, oacc[nd][1] * inv0);
        *reinterpret_cast<float2*>(&out[(size_t)(row0 + 8) * DMODEL + col]) =
            make_float2(oacc[nd][2] * inv1, oacc[nd][3] * inv1);
    }
}

// ===========================================================================
extern "C" void kernel_launch(void* const* d_in, const int* in_sizes, int n_in,
                              void* d_out, int out_size)
{
    const float* x  = (const float*)d_in[0];
    const float* Wq = (const float*)d_in[1];
    const float* bq = (const float*)d_in[2];
    const float* Wk = (const float*)d_in[3];
    const float* bk = (const float*)d_in[4];
    const float* Wv = (const float*)d_in[5];
    const float* bv = (const float*)d_in[6];
    float* out = (float*)d_out;

    void *qp, *kp, *vp;
    cudaGetSymbolAddress(&qp, g_q);
    cudaGetSymbolAddress(&kp, g_k);
    cudaGetSymbolAddress(&vp, g_v);

    // fold softmax scale and log2(e) into q so attention uses exp2
    const float qmul = 0.08838834764831845f * 1.4426950408889634f;

    mqa_gemm_fused<<<dim3(20, S_LEN / GBM), 256>>>(
        x, Wq, bq, Wk, bk, Wv, bv,
        (uint32_t*)qp, (uint32_t*)kp, (__half*)vp, qmul);

    mqa_flash3<<<dim3(S_LEN / 64, NH), 128>>>(out);
}